// round 4
// baseline (speedup 1.0000x reference)
#include <cuda_runtime.h>
#include <math.h>

// Problem constants
#define Bz   2
#define Sz   2048
#define Dz   1024
#define Hz   16
#define DHz  64
#define BLKz 128
#define NBz  16
#define Mz   (Bz * Sz)     // 4096 rows
#define FFz  (4 * Dz)      // 4096
#define KT   16            // k-tile depth

// ---------------- scratch (no dynamic allocation allowed) ----------------
__device__ float g_h  [Mz * Dz];
__device__ float g_q  [Mz * Dz];
__device__ float g_k  [Mz * Dz];
__device__ float g_v  [Mz * Dz];
__device__ float g_ctx[Mz * Dz];
__device__ float g_x1 [Mz * Dz];
__device__ float g_h2 [Mz * Dz];
__device__ float g_ff [(size_t)Mz * FFz];

// ---------------- cp.async helpers ----------------
__device__ __forceinline__ void cp_async16(void* smem_dst, const void* gmem_src) {
    unsigned sa = (unsigned)__cvta_generic_to_shared(smem_dst);
    asm volatile("cp.async.cg.shared.global [%0], [%1], 16;\n" :: "r"(sa), "l"(gmem_src));
}
__device__ __forceinline__ void cp_async_commit() {
    asm volatile("cp.async.commit_group;\n" ::: "memory");
}
__device__ __forceinline__ void cp_async_wait_all() {
    asm volatile("cp.async.wait_group 0;\n" ::: "memory");
}

// ---------------- LayerNorm: one 256-thread block per row ----------------
__global__ void __launch_bounds__(256) ln_kernel(
    const float* __restrict__ x, const float* __restrict__ gam,
    const float* __restrict__ bet, float* __restrict__ out)
{
    int row = blockIdx.x;
    int t = threadIdx.x;                       // 256 threads * float4 = 1024
    const float4* xr = (const float4*)(x + (size_t)row * Dz);
    float4 v = xr[t];
    float s  = v.x + v.y + v.z + v.w;
    float ss = v.x*v.x + v.y*v.y + v.z*v.z + v.w*v.w;
    #pragma unroll
    for (int o = 16; o > 0; o >>= 1) {
        s  += __shfl_xor_sync(0xFFFFFFFFu, s,  o);
        ss += __shfl_xor_sync(0xFFFFFFFFu, ss, o);
    }
    __shared__ float sh[16];
    int w = t >> 5, lane = t & 31;
    if (lane == 0) { sh[w] = s; sh[8 + w] = ss; }
    __syncthreads();
    if (t == 0) {
        float S = 0.f, SS = 0.f;
        #pragma unroll
        for (int i = 0; i < 8; ++i) { S += sh[i]; SS += sh[8 + i]; }
        sh[0] = S; sh[8] = SS;
    }
    __syncthreads();
    float mean = sh[0] * (1.0f / Dz);
    float var  = sh[8] * (1.0f / Dz) - mean * mean;
    float inv  = rsqrtf(var + 1e-5f);
    float4 gg = ((const float4*)gam)[t];
    float4 bb = ((const float4*)bet)[t];
    float4 o;
    o.x = (v.x - mean) * inv * gg.x + bb.x;
    o.y = (v.y - mean) * inv * gg.y + bb.y;
    o.z = (v.z - mean) * inv * gg.z + bb.z;
    o.w = (v.w - mean) * inv * gg.w + bb.w;
    ((float4*)(out + (size_t)row * Dz))[t] = o;
}

// ---------------- SGEMM core: 128x128xKT tiles, double-buffered ----------------
__device__ __forceinline__ float gelu_exact(float x) {
    return 0.5f * x * (1.0f + erff(x * 0.70710678118654752f));
}

// EPI: 0 = bias, 1 = bias + residual, 2 = bias + exact GeLU
template<int EPI>
__device__ __forceinline__ void sgemm_body(
    const float* __restrict__ A, const float* __restrict__ Bm,
    const float* __restrict__ bias, const float* __restrict__ Res,
    float* __restrict__ C, int N, int K, int bm, int bn)
{
    __shared__ float As[2][KT][128];     // A stored transposed: As[k][m]
    __shared__ float Bs[2][KT][128];
    int tid = threadIdx.x;

    // A tile 128x16 = 512 float4 slots; thread owns slots tid, tid+256
    int ar0 = tid >> 2,         ac0 = (tid & 3) * 4;
    int ar1 = (tid + 256) >> 2, ac1 = ((tid + 256) & 3) * 4;
    // B tile 16x128 = 512 float4 slots (cp.async path, no transpose)
    int br0 = tid >> 5,         bc0 = (tid & 31) * 4;
    int br1 = (tid + 256) >> 5, bc1 = ((tid + 256) & 31) * 4;
    const float* Ap0 = A  + (size_t)(bm + ar0) * K + ac0;
    const float* Ap1 = A  + (size_t)(bm + ar1) * K + ac1;
    const float* Bp0 = Bm + (size_t)br0 * N + bn + bc0;
    const float* Bp1 = Bm + (size_t)br1 * N + bn + bc1;

    int tx = tid & 15, ty = tid >> 4;    // 16x16 threads, 8x8 microtile
    float acc[8][8];
    #pragma unroll
    for (int i = 0; i < 8; ++i)
        #pragma unroll
        for (int j = 0; j < 8; ++j) acc[i][j] = 0.f;

    // preload tile 0 into buffer 0
    {
        float4 a0 = *(const float4*)Ap0;
        float4 a1 = *(const float4*)Ap1;
        cp_async16(&Bs[0][br0][bc0], Bp0);
        cp_async16(&Bs[0][br1][bc1], Bp1);
        cp_async_commit();
        As[0][ac0 + 0][ar0] = a0.x; As[0][ac0 + 1][ar0] = a0.y;
        As[0][ac0 + 2][ar0] = a0.z; As[0][ac0 + 3][ar0] = a0.w;
        As[0][ac1 + 0][ar1] = a1.x; As[0][ac1 + 1][ar1] = a1.y;
        As[0][ac1 + 2][ar1] = a1.z; As[0][ac1 + 3][ar1] = a1.w;
    }
    cp_async_wait_all();
    __syncthreads();

    int nk = K / KT;
    for (int kt = 0; kt < nk; ++kt) {
        int p = kt & 1, q = 1 - p;
        float4 a0, a1;
        bool more = (kt + 1 < nk);
        if (more) {                                     // issue next-tile loads early
            size_t ko = (size_t)(kt + 1) * KT;
            a0 = *(const float4*)(Ap0 + ko);
            a1 = *(const float4*)(Ap1 + ko);
            cp_async16(&Bs[q][br0][bc0], Bp0 + ko * N);
            cp_async16(&Bs[q][br1][bc1], Bp1 + ko * N);
            cp_async_commit();
        }
        #pragma unroll
        for (int k = 0; k < KT; ++k) {                  // hides load latency
            float af[8], bf[8];
            *(float4*)(af)     = *(const float4*)&As[p][k][ty * 8];
            *(float4*)(af + 4) = *(const float4*)&As[p][k][ty * 8 + 4];
            *(float4*)(bf)     = *(const float4*)&Bs[p][k][tx * 8];
            *(float4*)(bf + 4) = *(const float4*)&Bs[p][k][tx * 8 + 4];
            #pragma unroll
            for (int i = 0; i < 8; ++i)
                #pragma unroll
                for (int j = 0; j < 8; ++j)
                    acc[i][j] += af[i] * bf[j];
        }
        if (more) {                                     // A into other buffer
            As[q][ac0 + 0][ar0] = a0.x; As[q][ac0 + 1][ar0] = a0.y;
            As[q][ac0 + 2][ar0] = a0.z; As[q][ac0 + 3][ar0] = a0.w;
            As[q][ac1 + 0][ar1] = a1.x; As[q][ac1 + 1][ar1] = a1.y;
            As[q][ac1 + 2][ar1] = a1.z; As[q][ac1 + 3][ar1] = a1.w;
        }
        cp_async_wait_all();
        __syncthreads();    // readers of buf p done; buf q stores visible
    }

    #pragma unroll
    for (int i = 0; i < 8; ++i) {
        int row = bm + ty * 8 + i;
        float*       cp = C + (size_t)row * N + bn + tx * 8;
        const float* rp = (EPI == 1) ? (Res + (size_t)row * N + bn + tx * 8) : (const float*)0;
        #pragma unroll
        for (int j = 0; j < 8; j += 4) {
            float4 bsv = *(const float4*)(bias + bn + tx * 8 + j);
            float4 o;
            o.x = acc[i][j + 0] + bsv.x;
            o.y = acc[i][j + 1] + bsv.y;
            o.z = acc[i][j + 2] + bsv.z;
            o.w = acc[i][j + 3] + bsv.w;
            if (EPI == 1) {
                float4 r4 = *(const float4*)(rp + j);
                o.x += r4.x; o.y += r4.y; o.z += r4.z; o.w += r4.w;
            }
            if (EPI == 2) {
                o.x = gelu_exact(o.x); o.y = gelu_exact(o.y);
                o.z = gelu_exact(o.z); o.w = gelu_exact(o.w);
            }
            *(float4*)(cp + j) = o;
        }
    }
}

template<int EPI>
__global__ void __launch_bounds__(256, 2) sgemm(
    const float* __restrict__ A, const float* __restrict__ Bm,
    const float* __restrict__ bias, const float* __restrict__ Res,
    float* __restrict__ C, int N, int K)
{
    sgemm_body<EPI>(A, Bm, bias, Res, C, N, K,
                    blockIdx.y * 128, blockIdx.x * 128);
}

// Fused QKV: gridDim.z in {0,1,2} selects (Wq,bq,q) / (Wk,bk,k) / (Wv,bv,v)
__global__ void __launch_bounds__(256, 2) qkv_gemm(
    const float* __restrict__ A,
    const float* __restrict__ Wq, const float* __restrict__ bq, float* __restrict__ Oq,
    const float* __restrict__ Wk, const float* __restrict__ bk, float* __restrict__ Ok,
    const float* __restrict__ Wv, const float* __restrict__ bv, float* __restrict__ Ov)
{
    const float* W; const float* bi; float* O;
    if (blockIdx.z == 0)      { W = Wq; bi = bq; O = Oq; }
    else if (blockIdx.z == 1) { W = Wk; bi = bk; O = Ok; }
    else                      { W = Wv; bi = bv; O = Ov; }
    sgemm_body<0>(A, W, bi, (const float*)0, O, Dz, Dz,
                  blockIdx.y * 128, blockIdx.x * 128);
}

// ---------------- block-sparse causal attention ----------------
// grid = (NB, H, B); 128 threads; thread t owns query row t of block ib.
// K/V block staged in 64KB dynamic smem; all smem reads are warp-broadcast.
__global__ void __launch_bounds__(128) attn_kernel(
    const float* __restrict__ q, const float* __restrict__ k,
    const float* __restrict__ v, const int* __restrict__ layout,
    float* __restrict__ ctx)
{
    extern __shared__ float sm[];
    float* Ks = sm;                  // [128][64]
    float* Vs = sm + BLKz * DHz;     // [128][64]
    int ib = blockIdx.x, h = blockIdx.y, b = blockIdx.z;
    int t  = threadIdx.x;
    size_t row = (size_t)b * Sz + (size_t)ib * BLKz + t;

    float qr[DHz];
    {
        const float* qp = q + row * Dz + h * DHz;
        #pragma unroll
        for (int c = 0; c < 16; ++c) *(float4*)(qr + 4 * c) = *(const float4*)(qp + 4 * c);
        #pragma unroll
        for (int d = 0; d < DHz; ++d) qr[d] *= 0.125f;   // DH^-0.5
    }

    float mrow = -INFINITY, l = 0.f;
    float acc[DHz];
    #pragma unroll
    for (int d = 0; d < DHz; ++d) acc[d] = 0.f;

    const int* lay = layout + (h * NBz + ib) * NBz;
    for (int j = 0; j <= ib; ++j) {
        if (lay[j] == 0) continue;               // uniform across CTA
        __syncthreads();                         // prior block reads done
        #pragma unroll
        for (int it = 0; it < 16; ++it) {        // coop load 128x64 K and V
            int e  = it * 128 + t;
            int r  = e >> 4, c4 = (e & 15) << 2;
            size_t g = ((size_t)b * Sz + (size_t)j * BLKz + r) * Dz + h * DHz + c4;
            *(float4*)(Ks + r * DHz + c4) = *(const float4*)(k + g);
            *(float4*)(Vs + r * DHz + c4) = *(const float4*)(v + g);
        }
        __syncthreads();

        int kmax = (j == ib) ? t : (BLKz - 1);   // inclusive causal limit
        for (int c0 = 0; c0 <= kmax; c0 += 16) {
            int lim = kmax - c0;                 // >= 0
            float sarr[16];
            float cmax = -INFINITY;
            #pragma unroll
            for (int u = 0; u < 16; ++u) {
                float s = -INFINITY;
                if (u <= lim) {
                    const float* kr = Ks + (c0 + u) * DHz;
                    float a0 = 0.f, a1 = 0.f, a2 = 0.f, a3 = 0.f;
                    #pragma unroll
                    for (int c = 0; c < 16; ++c) {
                        float4 kv = *(const float4*)(kr + 4 * c);
                        a0 += qr[4 * c + 0] * kv.x;
                        a1 += qr[4 * c + 1] * kv.y;
                        a2 += qr[4 * c + 2] * kv.z;
                        a3 += qr[4 * c + 3] * kv.w;
                    }
                    s = (a0 + a1) + (a2 + a3);
                    cmax = fmaxf(cmax, s);
                }
                sarr[u] = s;
            }
            float mnew = fmaxf(mrow, cmax);
            float corr = (mrow == -INFINITY) ? 0.f : __expf(mrow - mnew);
            l *= corr;
            #pragma unroll
            for (int d = 0; d < DHz; ++d) acc[d] *= corr;
            #pragma unroll
            for (int u = 0; u < 16; ++u) {
                if (u <= lim) {
                    float p = __expf(sarr[u] - mnew);
                    l += p;
                    const float* vr = Vs + (c0 + u) * DHz;
                    #pragma unroll
                    for (int c = 0; c < 16; ++c) {
                        float4 vv = *(const float4*)(vr + 4 * c);
                        acc[4 * c + 0] += p * vv.x;
                        acc[4 * c + 1] += p * vv.y;
                        acc[4 * c + 2] += p * vv.z;
                        acc[4 * c + 3] += p * vv.w;
                    }
                }
            }
            mrow = mnew;
        }
    }

    float invl = 1.0f / l;
    float* op = ctx + row * Dz + h * DHz;
    #pragma unroll
    for (int c = 0; c < 16; ++c) {
        float4 o;
        o.x = acc[4 * c + 0] * invl;
        o.y = acc[4 * c + 1] * invl;
        o.z = acc[4 * c + 2] * invl;
        o.w = acc[4 * c + 3] * invl;
        *(float4*)(op + 4 * c) = o;
    }
}

// ---------------- launcher ----------------
extern "C" void kernel_launch(void* const* d_in, const int* in_sizes, int n_in,
                              void* d_out, int out_size)
{
    const float* x     = (const float*)d_in[0];
    const float* ln1_g = (const float*)d_in[1];
    const float* ln1_b = (const float*)d_in[2];
    const float* Wq    = (const float*)d_in[3];
    const float* bq    = (const float*)d_in[4];
    const float* Wk    = (const float*)d_in[5];
    const float* bk    = (const float*)d_in[6];
    const float* Wv    = (const float*)d_in[7];
    const float* bv    = (const float*)d_in[8];
    const float* Wo    = (const float*)d_in[9];
    const float* bo    = (const float*)d_in[10];
    const float* ln2_g = (const float*)d_in[11];
    const float* ln2_b = (const float*)d_in[12];
    const float* W1    = (const float*)d_in[13];
    const float* b1    = (const float*)d_in[14];
    const float* W2    = (const float*)d_in[15];
    const float* b2    = (const float*)d_in[16];
    const int*   layout= (const int*)  d_in[17];
    float* out = (float*)d_out;

    float *h, *qq, *kk, *vv, *ctxp, *x1, *h2, *ff;
    cudaGetSymbolAddress((void**)&h,    g_h);
    cudaGetSymbolAddress((void**)&qq,   g_q);
    cudaGetSymbolAddress((void**)&kk,   g_k);
    cudaGetSymbolAddress((void**)&vv,   g_v);
    cudaGetSymbolAddress((void**)&ctxp, g_ctx);
    cudaGetSymbolAddress((void**)&x1,   g_x1);
    cudaGetSymbolAddress((void**)&h2,   g_h2);
    cudaGetSymbolAddress((void**)&ff,   g_ff);

    // 1. h = LN1(x)
    ln_kernel<<<Mz, 256>>>(x, ln1_g, ln1_b, h);

    // 2. fused q/k/v = h @ W{q,k,v} + b  (grid.z selects projection)
    dim3 gq(Dz / 128, Mz / 128, 3);
    qkv_gemm<<<gq, 256>>>(h, Wq, bq, qq, Wk, bk, kk, Wv, bv, vv);

    // 3. block-sparse attention -> ctx [B,S,D]
    int smem_bytes = 2 * BLKz * DHz * (int)sizeof(float);   // 64 KB
    cudaFuncSetAttribute(attn_kernel, cudaFuncAttributeMaxDynamicSharedMemorySize, smem_bytes);
    attn_kernel<<<dim3(NBz, Hz, Bz), 128, smem_bytes>>>(qq, kk, vv, layout, ctxp);

    // 4. x1 = x + ctx @ Wo + bo
    dim3 g1(Dz / 128, Mz / 128);
    sgemm<1><<<g1, 256>>>(ctxp, Wo, bo, x, x1, Dz, Dz);

    // 5. h2 = LN2(x1)
    ln_kernel<<<Mz, 256>>>(x1, ln2_g, ln2_b, h2);

    // 6. ff = gelu(h2 @ W1 + b1)
    dim3 g2(FFz / 128, Mz / 128);
    sgemm<2><<<g2, 256>>>(h2, W1, b1, (const float*)0, ff, FFz, Dz);

    // 7. out = x1 + ff @ W2 + b2
    sgemm<1><<<g1, 256>>>(ff, W2, b2, x1, out, Dz, FFz);
}

// round 14
// speedup vs baseline: 2.0344x; 2.0344x over previous
#include <cuda_runtime.h>
#include <cuda_bf16.h>
#include <math.h>
#include <stdint.h>

// Problem constants
#define Bz   2
#define Sz   2048
#define Dz   1024
#define Hz   16
#define DHz  64
#define BLKz 128
#define NBz  16
#define Mz   (Bz * Sz)     // 4096 rows
#define FFz  (4 * Dz)      // 4096

typedef __nv_bfloat16 bf16;

// ---------------- scratch (no dynamic allocation allowed) ----------------
__device__ __align__(256) bf16 g_h_hi [Mz * Dz];
__device__ __align__(256) bf16 g_h_lo [Mz * Dz];
__device__ __align__(256) bf16 g_h2_hi[Mz * Dz];
__device__ __align__(256) bf16 g_h2_lo[Mz * Dz];
__device__ __align__(256) bf16 g_cx_hi[Mz * Dz];
__device__ __align__(256) bf16 g_cx_lo[Mz * Dz];
__device__ __align__(256) bf16 g_ff_hi[(size_t)Mz * FFz];
__device__ __align__(256) bf16 g_ff_lo[(size_t)Mz * FFz];
__device__ __align__(256) bf16 g_wqt_hi[Dz * Dz];
__device__ __align__(256) bf16 g_wqt_lo[Dz * Dz];
__device__ __align__(256) bf16 g_wkt_hi[Dz * Dz];
__device__ __align__(256) bf16 g_wkt_lo[Dz * Dz];
__device__ __align__(256) bf16 g_wvt_hi[Dz * Dz];
__device__ __align__(256) bf16 g_wvt_lo[Dz * Dz];
__device__ __align__(256) bf16 g_wot_hi[Dz * Dz];
__device__ __align__(256) bf16 g_wot_lo[Dz * Dz];
__device__ __align__(256) bf16 g_w1t_hi[(size_t)Dz * FFz];
__device__ __align__(256) bf16 g_w1t_lo[(size_t)Dz * FFz];
__device__ __align__(256) bf16 g_w2t_hi[(size_t)Dz * FFz];
__device__ __align__(256) bf16 g_w2t_lo[(size_t)Dz * FFz];
__device__ float g_q [Mz * Dz];
__device__ float g_k [Mz * Dz];
__device__ float g_v [Mz * Dz];
__device__ float g_x1[Mz * Dz];

// ---------------- helpers ----------------
__device__ __forceinline__ uint32_t smem_u32(const void* p) {
    uint32_t a;
    asm("{ .reg .u64 t; cvta.to.shared.u64 t, %1; cvt.u32.u64 %0, t; }" : "=r"(a) : "l"(p));
    return a;
}
__device__ __forceinline__ void cp16(uint32_t sa, const void* g) {
    asm volatile("cp.async.cg.shared.global [%0], [%1], 16;\n" :: "r"(sa), "l"(g));
}
__device__ __forceinline__ void cp_commit()   { asm volatile("cp.async.commit_group;\n" ::: "memory"); }
__device__ __forceinline__ void cp_wait_all() { asm volatile("cp.async.wait_group 0;\n" ::: "memory"); }

__device__ __forceinline__ void ldsm_x4(uint32_t& r0, uint32_t& r1, uint32_t& r2, uint32_t& r3,
                                        uint32_t addr) {
    asm volatile("ldmatrix.sync.aligned.m8n8.x4.shared.b16 {%0,%1,%2,%3}, [%4];"
                 : "=r"(r0), "=r"(r1), "=r"(r2), "=r"(r3) : "r"(addr));
}
__device__ __forceinline__ void ldsm_x2(uint32_t& r0, uint32_t& r1, uint32_t addr) {
    asm volatile("ldmatrix.sync.aligned.m8n8.x2.shared.b16 {%0,%1}, [%2];"
                 : "=r"(r0), "=r"(r1) : "r"(addr));
}
__device__ __forceinline__ void mma16816(float* d, const uint32_t* a, const uint32_t* b) {
    asm volatile("mma.sync.aligned.m16n8k16.row.col.f32.bf16.bf16.f32 "
                 "{%0,%1,%2,%3}, {%4,%5,%6,%7}, {%8,%9}, {%0,%1,%2,%3};"
                 : "+f"(d[0]), "+f"(d[1]), "+f"(d[2]), "+f"(d[3])
                 : "r"(a[0]), "r"(a[1]), "r"(a[2]), "r"(a[3]), "r"(b[0]), "r"(b[1]));
}

__device__ __forceinline__ float gelu_exact(float x) {
    return 0.5f * x * (1.0f + erff(x * 0.70710678118654752f));
}
__device__ __forceinline__ void split_store(bf16* hi, bf16* lo, size_t idx, float v) {
    bf16 h = __float2bfloat16(v);
    hi[idx] = h;
    lo[idx] = __float2bfloat16(v - __bfloat162float(h));
}

// ---------------- LayerNorm -> hi/lo bf16 ----------------
__global__ void __launch_bounds__(256) ln_split_kernel(
    const float* __restrict__ x, const float* __restrict__ gam,
    const float* __restrict__ bet, bf16* __restrict__ ohi, bf16* __restrict__ olo)
{
    int row = blockIdx.x;
    int t = threadIdx.x;
    const float4* xr = (const float4*)(x + (size_t)row * Dz);
    float4 v = xr[t];
    float s  = v.x + v.y + v.z + v.w;
    float ss = v.x*v.x + v.y*v.y + v.z*v.z + v.w*v.w;
    #pragma unroll
    for (int o = 16; o > 0; o >>= 1) {
        s  += __shfl_xor_sync(0xFFFFFFFFu, s,  o);
        ss += __shfl_xor_sync(0xFFFFFFFFu, ss, o);
    }
    __shared__ float sh[16];
    int w = t >> 5, lane = t & 31;
    if (lane == 0) { sh[w] = s; sh[8 + w] = ss; }
    __syncthreads();
    if (t == 0) {
        float S = 0.f, SS = 0.f;
        #pragma unroll
        for (int i = 0; i < 8; ++i) { S += sh[i]; SS += sh[8 + i]; }
        sh[0] = S; sh[8] = SS;
    }
    __syncthreads();
    float mean = sh[0] * (1.0f / Dz);
    float var  = sh[8] * (1.0f / Dz) - mean * mean;
    float inv  = rsqrtf(var + 1e-5f);
    float4 gg = ((const float4*)gam)[t];
    float4 bb = ((const float4*)bet)[t];
    float o0 = (v.x - mean) * inv * gg.x + bb.x;
    float o1 = (v.y - mean) * inv * gg.y + bb.y;
    float o2 = (v.z - mean) * inv * gg.z + bb.z;
    float o3 = (v.w - mean) * inv * gg.w + bb.w;
    size_t base = (size_t)row * Dz + t * 4;
    split_store(ohi, olo, base + 0, o0);
    split_store(ohi, olo, base + 1, o1);
    split_store(ohi, olo, base + 2, o2);
    split_store(ohi, olo, base + 3, o3);
}

// ---------------- transpose + split: W[K,N] -> Wt_hi/lo[N,K] ----------------
__global__ void __launch_bounds__(256) tsplit_kernel(
    const float* __restrict__ W, bf16* __restrict__ hi, bf16* __restrict__ lo,
    int K, int N)
{
    __shared__ float tile[32][33];
    int n0 = blockIdx.x * 32, k0 = blockIdx.y * 32;
    int tx = threadIdx.x & 31, ty = threadIdx.x >> 5;   // 32x8
    #pragma unroll
    for (int j = 0; j < 4; ++j)
        tile[ty + j * 8][tx] = W[(size_t)(k0 + ty + j * 8) * N + n0 + tx];
    __syncthreads();
    #pragma unroll
    for (int j = 0; j < 4; ++j) {
        float v = tile[tx][ty + j * 8];                 // W[k0+tx][n0+ty+j*8]
        size_t idx = (size_t)(n0 + ty + j * 8) * K + k0 + tx;
        bf16 h = __float2bfloat16(v);
        hi[idx] = h;
        lo[idx] = __float2bfloat16(v - __bfloat162float(h));
    }
}

// ---------------- mma.sync bf16-split GEMM ----------------
// D[m][n] = sum_k A[m][k]*Bt[n][k]; A = Ahi+Alo, Bt = Bhi+Blo (3 passes).
// CTA 128x128, K-tile 64. 8 warps in 2x4; warp tile 64x32 (4x4 m16n8k16 frags).
// Smem: row-major [128][64] padded to 72 elems (144B rows; ldmatrix conflict-free).
// EPI: 0 = bias -> f32; 1 = bias + residual -> f32; 2 = bias + GeLU -> hi/lo bf16
#define RS        72
#define MAT_BYTES (128 * RS * 2)          // 18432
#define STG_BYTES (4 * MAT_BYTES)         // 73728
#define TCG_SMEM  (2 * STG_BYTES)         // 147456

template<int EPI>
__global__ void __launch_bounds__(256, 1) tc_gemm(
    const bf16* __restrict__ Ahi, const bf16* __restrict__ Alo,
    const bf16* __restrict__ Bhi, const bf16* __restrict__ Blo,
    const float* __restrict__ bias, const float* __restrict__ Res,
    float* __restrict__ Cf, bf16* __restrict__ Chi, bf16* __restrict__ Clo,
    int N, int K)
{
    extern __shared__ char smem[];
    uint32_t sb = smem_u32(smem);
    int tid = threadIdx.x, wid = tid >> 5, lane = tid & 31;
    int bn = blockIdx.x * 128, bm = blockIdx.y * 128;
    int warp_m = wid >> 2, warp_n = wid & 3;            // 2 x 4 warps

    float acc[4][4][4];
    #pragma unroll
    for (int i = 0; i < 4; ++i)
        #pragma unroll
        for (int j = 0; j < 4; ++j)
            #pragma unroll
            for (int e = 0; e < 4; ++e) acc[i][j][e] = 0.f;

    // stage s: Ahi | Alo | Bhi | Blo, each 128 rows x 72 bf16 (144B rows)
    #define LOAD_STAGE(kt, s) do {                                              \
        uint32_t _b = sb + (uint32_t)(s) * STG_BYTES;                           \
        _Pragma("unroll")                                                       \
        for (int _i = 0; _i < 4; ++_i) {                                        \
            int _cid = tid + 256 * _i;          /* 0..1023 */                   \
            int _row = _cid >> 3, _c = _cid & 7;                                \
            uint32_t _so = (uint32_t)(_row * 144 + _c * 16);                    \
            size_t _ga = (size_t)(bm + _row) * K + (size_t)(kt) * 64 + _c * 8;  \
            size_t _gb = (size_t)(bn + _row) * K + (size_t)(kt) * 64 + _c * 8;  \
            cp16(_b                 + _so, Ahi + _ga);                          \
            cp16(_b + MAT_BYTES     + _so, Alo + _ga);                          \
            cp16(_b + 2 * MAT_BYTES + _so, Bhi + _gb);                          \
            cp16(_b + 3 * MAT_BYTES + _so, Blo + _gb);                          \
        }                                                                       \
        cp_commit();                                                            \
    } while (0)

    LOAD_STAGE(0, 0);
    cp_wait_all();
    __syncthreads();

    // ldmatrix lane addressing (canonical patterns)
    int a_row = lane & 15;                 // 0..15
    int a_col = (lane >> 4) << 3;          // 0 or 8
    int b_row = lane & 7;                  // 0..7
    int b_col = ((lane >> 3) & 1) << 3;    // 0 or 8 (lanes 0-15 meaningful)

    int nt_tiles = K / 64;
    for (int t = 0; t < nt_tiles; ++t) {
        int p = t & 1;
        if (t + 1 < nt_tiles) LOAD_STAGE(t + 1, 1 - p);

        uint32_t base = sb + (uint32_t)p * STG_BYTES;
        #pragma unroll
        for (int c = 0; c < 4; ++c) {       // k16 chunks within k-tile 64
            uint32_t ah[4][4], al[4][4], bh[4][2], bl[4][2];
            #pragma unroll
            for (int mt = 0; mt < 4; ++mt) {
                uint32_t off = (uint32_t)((warp_m * 64 + mt * 16 + a_row) * 144
                                          + (c * 16 + a_col) * 2);
                ldsm_x4(ah[mt][0], ah[mt][1], ah[mt][2], ah[mt][3], base + off);
                ldsm_x4(al[mt][0], al[mt][1], al[mt][2], al[mt][3],
                        base + MAT_BYTES + off);
            }
            #pragma unroll
            for (int nt = 0; nt < 4; ++nt) {
                uint32_t off = (uint32_t)((warp_n * 32 + nt * 8 + b_row) * 144
                                          + (c * 16 + b_col) * 2);
                ldsm_x2(bh[nt][0], bh[nt][1], base + 2 * MAT_BYTES + off);
                ldsm_x2(bl[nt][0], bl[nt][1], base + 3 * MAT_BYTES + off);
            }
            #pragma unroll
            for (int mt = 0; mt < 4; ++mt)
                #pragma unroll
                for (int nt = 0; nt < 4; ++nt) {
                    mma16816(acc[mt][nt], ah[mt], bh[nt]);
                    mma16816(acc[mt][nt], ah[mt], bl[nt]);
                    mma16816(acc[mt][nt], al[mt], bh[nt]);
                }
        }
        cp_wait_all();
        __syncthreads();
    }

    // epilogue: fragment thread t holds D[t/4][(t%4)*2 (+1)] and D[t/4+8][...]
    int er = lane >> 2, ec = (lane & 3) * 2;
    #pragma unroll
    for (int mt = 0; mt < 4; ++mt) {
        #pragma unroll
        for (int nt = 0; nt < 4; ++nt) {
            int c0 = bn + warp_n * 32 + nt * 8 + ec;
            float bs0 = bias[c0], bs1 = bias[c0 + 1];
            #pragma unroll
            for (int half = 0; half < 2; ++half) {
                int row = bm + warp_m * 64 + mt * 16 + er + half * 8;
                float v0 = acc[mt][nt][half * 2 + 0] + bs0;
                float v1 = acc[mt][nt][half * 2 + 1] + bs1;
                if (EPI == 1) {
                    const float2 r2 = *(const float2*)(Res + (size_t)row * N + c0);
                    v0 += r2.x; v1 += r2.y;
                }
                if (EPI == 2) { v0 = gelu_exact(v0); v1 = gelu_exact(v1); }
                if (EPI <= 1) {
                    float2 o; o.x = v0; o.y = v1;
                    *(float2*)(Cf + (size_t)row * N + c0) = o;
                } else {
                    size_t idx = (size_t)row * N + c0;
                    bf16 h0 = __float2bfloat16(v0);
                    bf16 h1 = __float2bfloat16(v1);
                    __nv_bfloat162 hp; hp.x = h0; hp.y = h1;
                    __nv_bfloat162 lp;
                    lp.x = __float2bfloat16(v0 - __bfloat162float(h0));
                    lp.y = __float2bfloat16(v1 - __bfloat162float(h1));
                    *(__nv_bfloat162*)(Chi + idx) = hp;
                    *(__nv_bfloat162*)(Clo + idx) = lp;
                }
            }
        }
    }
}

// ---------------- block-sparse causal attention (fp32, writes hi/lo ctx) ----------------
__global__ void __launch_bounds__(128) attn_kernel(
    const float* __restrict__ q, const float* __restrict__ k,
    const float* __restrict__ v, const int* __restrict__ layout,
    bf16* __restrict__ chi, bf16* __restrict__ clo)
{
    extern __shared__ float sm[];
    float* Ks = sm;                  // [128][64]
    float* Vs = sm + BLKz * DHz;     // [128][64]
    int ib = blockIdx.x, h = blockIdx.y, b = blockIdx.z;
    int t  = threadIdx.x;
    size_t row = (size_t)b * Sz + (size_t)ib * BLKz + t;

    float qr[DHz];
    {
        const float* qp = q + row * Dz + h * DHz;
        #pragma unroll
        for (int c = 0; c < 16; ++c) *(float4*)(qr + 4 * c) = *(const float4*)(qp + 4 * c);
        #pragma unroll
        for (int d = 0; d < DHz; ++d) qr[d] *= 0.125f;   // DH^-0.5
    }

    float mrow = -INFINITY, l = 0.f;
    float acc[DHz];
    #pragma unroll
    for (int d = 0; d < DHz; ++d) acc[d] = 0.f;

    const int* lay = layout + (h * NBz + ib) * NBz;
    for (int j = 0; j <= ib; ++j) {
        if (lay[j] == 0) continue;
        __syncthreads();
        #pragma unroll
        for (int it = 0; it < 16; ++it) {
            int e  = it * 128 + t;
            int r  = e >> 4, c4 = (e & 15) << 2;
            size_t g = ((size_t)b * Sz + (size_t)j * BLKz + r) * Dz + h * DHz + c4;
            *(float4*)(Ks + r * DHz + c4) = *(const float4*)(k + g);
            *(float4*)(Vs + r * DHz + c4) = *(const float4*)(v + g);
        }
        __syncthreads();

        int kmax = (j == ib) ? t : (BLKz - 1);
        for (int c0 = 0; c0 <= kmax; c0 += 16) {
            int lim = kmax - c0;
            float sarr[16];
            float cmax = -INFINITY;
            #pragma unroll
            for (int u = 0; u < 16; ++u) {
                float s = -INFINITY;
                if (u <= lim) {
                    const float* kr = Ks + (c0 + u) * DHz;
                    float a0 = 0.f, a1 = 0.f, a2 = 0.f, a3 = 0.f;
                    #pragma unroll
                    for (int c = 0; c < 16; ++c) {
                        float4 kv = *(const float4*)(kr + 4 * c);
                        a0 += qr[4 * c + 0] * kv.x;
                        a1 += qr[4 * c + 1] * kv.y;
                        a2 += qr[4 * c + 2] * kv.z;
                        a3 += qr[4 * c + 3] * kv.w;
                    }
                    s = (a0 + a1) + (a2 + a3);
                    cmax = fmaxf(cmax, s);
                }
                sarr[u] = s;
            }
            float mnew = fmaxf(mrow, cmax);
            float corr = (mrow == -INFINITY) ? 0.f : __expf(mrow - mnew);
            l *= corr;
            #pragma unroll
            for (int d = 0; d < DHz; ++d) acc[d] *= corr;
            #pragma unroll
            for (int u = 0; u < 16; ++u) {
                if (u <= lim) {
                    float p = __expf(sarr[u] - mnew);
                    l += p;
                    const float* vr = Vs + (c0 + u) * DHz;
                    #pragma unroll
                    for (int c = 0; c < 16; ++c) {
                        float4 vv = *(const float4*)(vr + 4 * c);
                        acc[4 * c + 0] += p * vv.x;
                        acc[4 * c + 1] += p * vv.y;
                        acc[4 * c + 2] += p * vv.z;
                        acc[4 * c + 3] += p * vv.w;
                    }
                }
            }
            mrow = mnew;
        }
    }

    float invl = 1.0f / l;
    size_t ob = row * Dz + h * DHz;
    #pragma unroll
    for (int d = 0; d < DHz; ++d)
        split_store(chi, clo, ob + d, acc[d] * invl);
}

// ---------------- launcher ----------------
extern "C" void kernel_launch(void* const* d_in, const int* in_sizes, int n_in,
                              void* d_out, int out_size)
{
    const float* x     = (const float*)d_in[0];
    const float* ln1_g = (const float*)d_in[1];
    const float* ln1_b = (const float*)d_in[2];
    const float* Wq    = (const float*)d_in[3];
    const float* bq    = (const float*)d_in[4];
    const float* Wk    = (const float*)d_in[5];
    const float* bk    = (const float*)d_in[6];
    const float* Wv    = (const float*)d_in[7];
    const float* bv    = (const float*)d_in[8];
    const float* Wo    = (const float*)d_in[9];
    const float* bo    = (const float*)d_in[10];
    const float* ln2_g = (const float*)d_in[11];
    const float* ln2_b = (const float*)d_in[12];
    const float* W1    = (const float*)d_in[13];
    const float* b1    = (const float*)d_in[14];
    const float* W2    = (const float*)d_in[15];
    const float* b2    = (const float*)d_in[16];
    const int*   layout= (const int*)  d_in[17];
    float* out = (float*)d_out;

    bf16 *h_hi, *h_lo, *h2_hi, *h2_lo, *cx_hi, *cx_lo, *ff_hi, *ff_lo;
    bf16 *wqt_hi, *wqt_lo, *wkt_hi, *wkt_lo, *wvt_hi, *wvt_lo, *wot_hi, *wot_lo;
    bf16 *w1t_hi, *w1t_lo, *w2t_hi, *w2t_lo;
    float *qq, *kk, *vv, *x1;
    cudaGetSymbolAddress((void**)&h_hi,  g_h_hi);  cudaGetSymbolAddress((void**)&h_lo,  g_h_lo);
    cudaGetSymbolAddress((void**)&h2_hi, g_h2_hi); cudaGetSymbolAddress((void**)&h2_lo, g_h2_lo);
    cudaGetSymbolAddress((void**)&cx_hi, g_cx_hi); cudaGetSymbolAddress((void**)&cx_lo, g_cx_lo);
    cudaGetSymbolAddress((void**)&ff_hi, g_ff_hi); cudaGetSymbolAddress((void**)&ff_lo, g_ff_lo);
    cudaGetSymbolAddress((void**)&wqt_hi, g_wqt_hi); cudaGetSymbolAddress((void**)&wqt_lo, g_wqt_lo);
    cudaGetSymbolAddress((void**)&wkt_hi, g_wkt_hi); cudaGetSymbolAddress((void**)&wkt_lo, g_wkt_lo);
    cudaGetSymbolAddress((void**)&wvt_hi, g_wvt_hi); cudaGetSymbolAddress((void**)&wvt_lo, g_wvt_lo);
    cudaGetSymbolAddress((void**)&wot_hi, g_wot_hi); cudaGetSymbolAddress((void**)&wot_lo, g_wot_lo);
    cudaGetSymbolAddress((void**)&w1t_hi, g_w1t_hi); cudaGetSymbolAddress((void**)&w1t_lo, g_w1t_lo);
    cudaGetSymbolAddress((void**)&w2t_hi, g_w2t_hi); cudaGetSymbolAddress((void**)&w2t_lo, g_w2t_lo);
    cudaGetSymbolAddress((void**)&qq, g_q); cudaGetSymbolAddress((void**)&kk, g_k);
    cudaGetSymbolAddress((void**)&vv, g_v); cudaGetSymbolAddress((void**)&x1, g_x1);

    cudaFuncSetAttribute(tc_gemm<0>, cudaFuncAttributeMaxDynamicSharedMemorySize, TCG_SMEM);
    cudaFuncSetAttribute(tc_gemm<1>, cudaFuncAttributeMaxDynamicSharedMemorySize, TCG_SMEM);
    cudaFuncSetAttribute(tc_gemm<2>, cudaFuncAttributeMaxDynamicSharedMemorySize, TCG_SMEM);

    // weight transpose + split (each call; graph-capturable)
    tsplit_kernel<<<dim3(Dz/32, Dz/32), 256>>>(Wq, wqt_hi, wqt_lo, Dz, Dz);
    tsplit_kernel<<<dim3(Dz/32, Dz/32), 256>>>(Wk, wkt_hi, wkt_lo, Dz, Dz);
    tsplit_kernel<<<dim3(Dz/32, Dz/32), 256>>>(Wv, wvt_hi, wvt_lo, Dz, Dz);
    tsplit_kernel<<<dim3(Dz/32, Dz/32), 256>>>(Wo, wot_hi, wot_lo, Dz, Dz);
    tsplit_kernel<<<dim3(FFz/32, Dz/32), 256>>>(W1, w1t_hi, w1t_lo, Dz, FFz);
    tsplit_kernel<<<dim3(Dz/32, FFz/32), 256>>>(W2, w2t_hi, w2t_lo, FFz, Dz);

    // 1. h = LN1(x) -> hi/lo
    ln_split_kernel<<<Mz, 256>>>(x, ln1_g, ln1_b, h_hi, h_lo);

    // 2. q/k/v = h @ W + b  (f32 out)
    dim3 g1(Dz/128, Mz/128);
    tc_gemm<0><<<g1, 256, TCG_SMEM>>>(h_hi, h_lo, wqt_hi, wqt_lo, bq, (const float*)0,
                                      qq, (bf16*)0, (bf16*)0, Dz, Dz);
    tc_gemm<0><<<g1, 256, TCG_SMEM>>>(h_hi, h_lo, wkt_hi, wkt_lo, bk, (const float*)0,
                                      kk, (bf16*)0, (bf16*)0, Dz, Dz);
    tc_gemm<0><<<g1, 256, TCG_SMEM>>>(h_hi, h_lo, wvt_hi, wvt_lo, bv, (const float*)0,
                                      vv, (bf16*)0, (bf16*)0, Dz, Dz);

    // 3. block-sparse attention -> ctx hi/lo
    int smem_attn = 2 * BLKz * DHz * (int)sizeof(float);   // 64 KB
    cudaFuncSetAttribute(attn_kernel, cudaFuncAttributeMaxDynamicSharedMemorySize, smem_attn);
    attn_kernel<<<dim3(NBz, Hz, Bz), 128, smem_attn>>>(qq, kk, vv, layout, cx_hi, cx_lo);

    // 4. x1 = x + ctx @ Wo + bo
    tc_gemm<1><<<g1, 256, TCG_SMEM>>>(cx_hi, cx_lo, wot_hi, wot_lo, bo, x,
                                      x1, (bf16*)0, (bf16*)0, Dz, Dz);

    // 5. h2 = LN2(x1) -> hi/lo
    ln_split_kernel<<<Mz, 256>>>(x1, ln2_g, ln2_b, h2_hi, h2_lo);

    // 6. ff = gelu(h2 @ W1 + b1) -> hi/lo
    dim3 g2(FFz/128, Mz/128);
    tc_gemm<2><<<g2, 256, TCG_SMEM>>>(h2_hi, h2_lo, w1t_hi, w1t_lo, b1, (const float*)0,
                                      (float*)0, ff_hi, ff_lo, FFz, Dz);

    // 7. out = x1 + ff @ W2 + b2
    tc_gemm<1><<<g1, 256, TCG_SMEM>>>(ff_hi, ff_lo, w2t_hi, w2t_lo, b2, x1,
                                      out, (bf16*)0, (bf16*)0, Dz, FFz);
}